// round 10
// baseline (speedup 1.0000x reference)
#include <cuda_runtime.h>
#include <cuda_bf16.h>
#include <cstdint>

#define BATCH 4
#define SEQ   1370
#define NH    16
#define HD    64
#define HID   1024
#define NTOK  (BATCH * SEQ)   // 5480

// Scratch: projected Q/K/V in [B, NH, L, HD] layout.
__device__ float g_q[(size_t)BATCH * NH * SEQ * HD];
__device__ float g_k[(size_t)BATCH * NH * SEQ * HD];
__device__ float g_v[(size_t)BATCH * NH * SEQ * HD];

// Pre-split bf16 planes of X and W (hi = rn(x), lo = rn(x - hi)).
__device__ __nv_bfloat16 g_xh[(size_t)NTOK * HID];
__device__ __nv_bfloat16 g_xl[(size_t)NTOK * HID];
__device__ __nv_bfloat16 g_wh[(size_t)3 * HID * HID];   // rows: proj*1024 + outch
__device__ __nv_bfloat16 g_wl[(size_t)3 * HID * HID];

// ===========================================================================
// Helpers
// ===========================================================================
__device__ __forceinline__ uint32_t smem_u32(const void* p) {
    uint32_t a;
    asm("{ .reg .u64 t; cvta.to.shared.u64 t, %1; cvt.u32.u64 %0, t; }"
        : "=r"(a) : "l"(p));
    return a;
}

#define LDMX4(r, addr) \
    asm volatile("ldmatrix.sync.aligned.m8n8.x4.shared.b16 {%0,%1,%2,%3}, [%4];" \
        : "=r"((r)[0]), "=r"((r)[1]), "=r"((r)[2]), "=r"((r)[3]) : "r"(addr))

#define LDMX4T(r, addr) \
    asm volatile("ldmatrix.sync.aligned.m8n8.x4.trans.shared.b16 {%0,%1,%2,%3}, [%4];" \
        : "=r"((r)[0]), "=r"((r)[1]), "=r"((r)[2]), "=r"((r)[3]) : "r"(addr))

#define MMA16816(d, a, b0, b1) \
    asm volatile("mma.sync.aligned.m16n8k16.row.col.f32.bf16.bf16.f32 " \
        "{%0,%1,%2,%3}, {%4,%5,%6,%7}, {%8,%9}, {%0,%1,%2,%3};" \
        : "+f"((d)[0]), "+f"((d)[1]), "+f"((d)[2]), "+f"((d)[3]) \
        : "r"((a)[0]), "r"((a)[1]), "r"((a)[2]), "r"((a)[3]), "r"(b0), "r"(b1))

__device__ __forceinline__ uint32_t pack_bf16(float lo, float hi) {
    uint32_t r;
    asm("cvt.rn.bf16x2.f32 %0, %1, %2;" : "=r"(r) : "f"(hi), "f"(lo));
    return r;
}

__device__ __forceinline__ void cp16(uint32_t dst, const void* src, int sz) {
    asm volatile("cp.async.cg.shared.global [%0], [%1], 16, %2;"
                 :: "r"(dst), "l"(src), "r"(sz) : "memory");
}
#define CP_COMMIT() asm volatile("cp.async.commit_group;" ::: "memory")
#define CP_WAIT(n)  asm volatile("cp.async.wait_group %0;" :: "n"(n) : "memory")

// fp32x4 -> bf16 hi/lo planes, 8B each, to smem (used by flash).
__device__ __forceinline__ void split_sts(char* hp, char* lp, uint32_t off, float4 v) {
    __nv_bfloat16 h0 = __float2bfloat16_rn(v.x);
    __nv_bfloat16 h1 = __float2bfloat16_rn(v.y);
    __nv_bfloat16 h2 = __float2bfloat16_rn(v.z);
    __nv_bfloat16 h3 = __float2bfloat16_rn(v.w);
    float l0 = v.x - __bfloat162float(h0);
    float l1 = v.y - __bfloat162float(h1);
    float l2 = v.z - __bfloat162float(h2);
    float l3 = v.w - __bfloat162float(h3);
    __nv_bfloat162 hA = __halves2bfloat162(h0, h1);
    __nv_bfloat162 hB = __halves2bfloat162(h2, h3);
    uint32_t lA = pack_bf16(l0, l1);
    uint32_t lB = pack_bf16(l2, l3);
    *(uint2*)(hp + off) = make_uint2(*(uint32_t*)&hA, *(uint32_t*)&hB);
    *(uint2*)(lp + off) = make_uint2(lA, lB);
}

// ===========================================================================
// Phase 0: one-shot split of X and W into bf16 hi/lo planes (memory-bound).
// ===========================================================================
__global__ __launch_bounds__(256)
void convert_planes(const float* __restrict__ X,
                    const float* __restrict__ Wq,
                    const float* __restrict__ Wk,
                    const float* __restrict__ Wv)
{
    const size_t nx = (size_t)NTOK * HID / 4;
    const size_t nw = (size_t)3 * HID * HID / 4;
    size_t idx = (size_t)blockIdx.x * 256 + threadIdx.x;
    if (idx >= nx + nw) return;

    float4 v;
    __nv_bfloat16 *hp, *lp;
    size_t e;
    if (idx < nx) {
        v  = ((const float4*)X)[idx];
        hp = g_xh; lp = g_xl; e = idx * 4;
    } else {
        size_t w4   = idx - nx;
        int    proj = (int)(w4 / (size_t)(HID * HID / 4));
        size_t off  = w4 - (size_t)proj * (HID * HID / 4);
        const float* W = (proj == 0) ? Wq : (proj == 1) ? Wk : Wv;
        v  = ((const float4*)W)[off];
        hp = g_wh; lp = g_wl; e = w4 * 4;
    }
    __nv_bfloat16 h0 = __float2bfloat16_rn(v.x);
    __nv_bfloat16 h1 = __float2bfloat16_rn(v.y);
    __nv_bfloat16 h2 = __float2bfloat16_rn(v.z);
    __nv_bfloat16 h3 = __float2bfloat16_rn(v.w);
    __nv_bfloat162 hA = __halves2bfloat162(h0, h1);
    __nv_bfloat162 hB = __halves2bfloat162(h2, h3);
    uint32_t lA = pack_bf16(v.x - __bfloat162float(h0), v.y - __bfloat162float(h1));
    uint32_t lB = pack_bf16(v.z - __bfloat162float(h2), v.w - __bfloat162float(h3));
    *(uint2*)(hp + e) = make_uint2(*(uint32_t*)&hA, *(uint32_t*)&hB);
    *(uint2*)(lp + e) = make_uint2(lA, lB);
}

// ===========================================================================
// Phase 1: QKV projection GEMM on mma.sync reading pre-split bf16 planes.
// Block tile 128x128, 8 warps (4m x 2n), BK=32, 2-stage cp.async pipeline.
// Y = Xh*Wh + Xh*Wl + Xl*Wh  (fp32 accum; ll dropped, error ~2^-18)
// ===========================================================================
#define QBK     32
#define QROWB   80                    // 64B data + 16B pad per k-row slice
#define QPLANE  (128 * QROWB)         // 10240 B
#define QBUF    (4 * QPLANE)          // Ah | Al | Bh | Bl = 40960 B
#define QK_SMEM (2 * QBUF)            // 81920 B
#define QCHUNKS (HID / QBK)           // 32

__global__ __launch_bounds__(256)
void qkv_mma(const float* __restrict__ bq,
             const float* __restrict__ bk,
             const float* __restrict__ bv)
{
    extern __shared__ char sm[];
    const uint32_t sbase = smem_u32(sm);

    const int tid  = threadIdx.x;
    const int lane = tid & 31;
    const int wid  = tid >> 5;
    const int wm   = wid & 3;
    const int wn   = wid >> 2;

    const int m0   = blockIdx.x * 128;
    const int nb   = blockIdx.y;      // 0..23
    const int proj = nb >> 3;
    const int o0   = (nb & 7) * 128;

    const float* bias = (proj == 0) ? bq : (proj == 1) ? bk : bv;
    float*       dst  = (proj == 0) ? g_q : (proj == 1) ? g_k : g_v;
    const int    wrow0 = proj * 1024 + o0;   // row base in g_wh/g_wl

    float acc[2][8][4];
    #pragma unroll
    for (int mt = 0; mt < 2; mt++)
        #pragma unroll
        for (int nt = 0; nt < 8; nt++)
            #pragma unroll
            for (int r = 0; r < 4; r++) acc[mt][nt][r] = 0.f;

    const uint32_t lmA = (uint32_t)((wm * 32 + (lane & 15)) * QROWB + (lane >> 4) * 16);
    const uint32_t lmB = (uint32_t)((wn * 64 + (lane & 15)) * QROWB + (lane >> 4) * 16);

    // cp.async issue of chunk c into buffer b: per thread 2 ops x 4 planes.
    // op id o in [0,512): row = o>>2 (0..127), seg = o&3 (16B within 64B row).
    auto issue = [&](int c, int b) {
        const int kc = c * QBK;
        #pragma unroll
        for (int i = 0; i < 2; i++) {
            int o   = i * 256 + tid;
            int row = o >> 2;
            int seg = o & 3;
            uint32_t dA = sbase + b * QBUF + (uint32_t)(row * QROWB + seg * 16);
            uint32_t dB = dA + 2 * QPLANE;
            size_t ax = (size_t)(m0 + row) * HID + kc + seg * 8;
            size_t bx = (size_t)(wrow0 + row) * HID + kc + seg * 8;
            int szA = (m0 + row < NTOK) ? 16 : 0;
            cp16(dA,          g_xh + ax, szA);
            cp16(dA + QPLANE, g_xl + ax, szA);
            cp16(dB,          g_wh + bx, 16);
            cp16(dB + QPLANE, g_wl + bx, 16);
        }
        CP_COMMIT();
    };

    issue(0, 0);

    for (int c = 0; c < QCHUNKS; c++) {
        if (c + 1 < QCHUNKS) {
            issue(c + 1, (c + 1) & 1);
            CP_WAIT(1);       // chunk c's group complete
        } else {
            CP_WAIT(0);
        }
        __syncthreads();

        const uint32_t Ahb = sbase + (c & 1) * QBUF;
        const uint32_t Alb = Ahb + QPLANE;
        const uint32_t Bhb = Ahb + 2 * QPLANE;
        const uint32_t Blb = Ahb + 3 * QPLANE;

        #pragma unroll
        for (int kk = 0; kk < 2; kk++) {
            const uint32_t kb = kk * 32;
            uint32_t fAh[2][4], fAl[2][4], fB[4][4];
            #pragma unroll
            for (int mt = 0; mt < 2; mt++) {
                LDMX4(fAh[mt], Ahb + lmA + mt * (16 * QROWB) + kb);
                LDMX4(fAl[mt], Alb + lmA + mt * (16 * QROWB) + kb);
            }
            #pragma unroll
            for (int n2 = 0; n2 < 4; n2++)
                LDMX4(fB[n2], Bhb + lmB + n2 * (16 * QROWB) + kb);
            #pragma unroll
            for (int mt = 0; mt < 2; mt++)
                #pragma unroll
                for (int nt = 0; nt < 8; nt++)     // hi * hi
                    MMA16816(acc[mt][nt], fAh[mt], fB[nt >> 1][nt & 1], fB[nt >> 1][2 + (nt & 1)]);
            #pragma unroll
            for (int mt = 0; mt < 2; mt++)
                #pragma unroll
                for (int nt = 0; nt < 8; nt++)     // lo * hi
                    MMA16816(acc[mt][nt], fAl[mt], fB[nt >> 1][nt & 1], fB[nt >> 1][2 + (nt & 1)]);
            #pragma unroll
            for (int n2 = 0; n2 < 4; n2++)
                LDMX4(fB[n2], Blb + lmB + n2 * (16 * QROWB) + kb);
            #pragma unroll
            for (int mt = 0; mt < 2; mt++)
                #pragma unroll
                for (int nt = 0; nt < 8; nt++)     // hi * lo
                    MMA16816(acc[mt][nt], fAh[mt], fB[nt >> 1][nt & 1], fB[nt >> 1][2 + (nt & 1)]);
        }
        __syncthreads();   // ldmatrix reads done before next issue overwrites
    }

    // ---- epilogue: bias add + scatter to [B, NH, L, HD] ----
    const int g   = lane >> 2;
    const int tig = lane & 3;
    const int headBase = (o0 + wn * 64) >> 6;
    #pragma unroll
    for (int mt = 0; mt < 2; mt++) {
        #pragma unroll
        for (int half = 0; half < 2; half++) {
            int gm = m0 + wm * 32 + mt * 16 + g + half * 8;
            if (gm >= NTOK) continue;
            int bb = gm / SEQ;
            int ll = gm - bb * SEQ;
            float* dp = dst + (((size_t)bb * NH + headBase) * SEQ + ll) * HD;
            #pragma unroll
            for (int nt = 0; nt < 8; nt++) {
                int dd = nt * 8 + tig * 2;
                float2 bv = *(const float2*)(bias + o0 + wn * 64 + dd);
                float2 ov;
                ov.x = acc[mt][nt][half * 2 + 0] + bv.x;
                ov.y = acc[mt][nt][half * 2 + 1] + bv.y;
                *(float2*)(dp + dd) = ov;
            }
        }
    }
}

// ===========================================================================
// Phase 2: flash attention on mma.sync (unchanged from R8 — 284us measured).
// ===========================================================================
#define FROWB 144
#define FA_QH 0
#define FA_QL (128 * FROWB)
#define FA_KH (2 * 128 * FROWB)
#define FA_KL (FA_KH + 64 * FROWB)
#define FA_VH (FA_KL + 64 * FROWB)
#define FA_VL (FA_VH + 64 * FROWB)
#define FA_SMEM (FA_VL + 64 * FROWB)        // 73728

__global__ __launch_bounds__(256)
void flash_mma(float* __restrict__ out)
{
    extern __shared__ char sm[];
    const uint32_t sb = smem_u32(sm);

    const int tid  = threadIdx.x;
    const int lane = tid & 31;
    const int w    = tid >> 5;

    const int qt    = blockIdx.x;
    const int bh    = blockIdx.y;
    const int batch = bh >> 4;
    const int head  = bh & 15;
    const float* Q = g_q + (size_t)bh * SEQ * HD;
    const float* K = g_k + (size_t)bh * SEQ * HD;
    const float* V = g_v + (size_t)bh * SEQ * HD;
    const int q0 = qt * 128;

    #pragma unroll
    for (int i = 0; i < 8; i++) {
        int f   = i * 256 + tid;
        int row = f >> 4;
        int c4  = (f & 15) << 2;
        int gq  = q0 + row;
        float4 v = (gq < SEQ)
            ? *(const float4*)(Q + (size_t)gq * HD + c4)
            : make_float4(0.f, 0.f, 0.f, 0.f);
        v.x *= 0.125f; v.y *= 0.125f; v.z *= 0.125f; v.w *= 0.125f;
        split_sts(sm + FA_QH, sm + FA_QL, (uint32_t)(row * FROWB + c4 * 2), v);
    }

    const uint32_t lmQ  = (uint32_t)((w * 16 + (lane & 15)) * FROWB + (lane >> 4) * 16);
    const uint32_t lmKV = (uint32_t)((lane & 15) * FROWB + (lane >> 4) * 16);
    const int g   = lane >> 2;
    const int tig = lane & 3;

    float m0v = -1e30f, m1v = -1e30f, l0v = 0.f, l1v = 0.f;
    float O[8][4];
    #pragma unroll
    for (int nt = 0; nt < 8; nt++)
        #pragma unroll
        for (int r = 0; r < 4; r++) O[nt][r] = 0.f;

    for (int kv0 = 0; kv0 < SEQ; kv0 += 64) {
        __syncthreads();

        #pragma unroll
        for (int i = 0; i < 4; i++) {
            int f   = i * 256 + tid;
            int row = f >> 4;
            int c4  = (f & 15) << 2;
            int gk  = kv0 + row;
            float4 vk, vv;
            if (gk < SEQ) {
                vk = *(const float4*)(K + (size_t)gk * HD + c4);
                vv = *(const float4*)(V + (size_t)gk * HD + c4);
            } else {
                vk = make_float4(0.f, 0.f, 0.f, 0.f);
                vv = vk;
            }
            uint32_t off = (uint32_t)(row * FROWB + c4 * 2);
            split_sts(sm + FA_KH, sm + FA_KL, off, vk);
            split_sts(sm + FA_VH, sm + FA_VL, off, vv);
        }
        __syncthreads();

        float S[8][4];
        #pragma unroll
        for (int nt = 0; nt < 8; nt++)
            #pragma unroll
            for (int r = 0; r < 4; r++) S[nt][r] = 0.f;

        #pragma unroll
        for (int ks = 0; ks < 4; ks++) {
            uint32_t qh[4], ql[4];
            LDMX4(qh, sb + FA_QH + lmQ + ks * 32);
            LDMX4(ql, sb + FA_QL + lmQ + ks * 32);
            #pragma unroll
            for (int n16 = 0; n16 < 4; n16++) {
                uint32_t kh[4], kl[4];
                LDMX4(kh, sb + FA_KH + lmKV + n16 * (16 * FROWB) + ks * 32);
                LDMX4(kl, sb + FA_KL + lmKV + n16 * (16 * FROWB) + ks * 32);
                MMA16816(S[2*n16],   qh, kh[0], kh[2]);
                MMA16816(S[2*n16+1], qh, kh[1], kh[3]);
                MMA16816(S[2*n16],   qh, kl[0], kl[2]);
                MMA16816(S[2*n16+1], qh, kl[1], kl[3]);
                MMA16816(S[2*n16],   ql, kh[0], kh[2]);
                MMA16816(S[2*n16+1], ql, kh[1], kh[3]);
            }
        }

        if (kv0 + 64 > SEQ) {
            #pragma unroll
            for (int nt = 0; nt < 8; nt++)
                #pragma unroll
                for (int e = 0; e < 4; e++)
                    if (kv0 + nt * 8 + tig * 2 + (e & 1) >= SEQ) S[nt][e] = -1e30f;
        }

        float mx0 = -1e30f, mx1 = -1e30f;
        #pragma unroll
        for (int nt = 0; nt < 8; nt++) {
            mx0 = fmaxf(mx0, fmaxf(S[nt][0], S[nt][1]));
            mx1 = fmaxf(mx1, fmaxf(S[nt][2], S[nt][3]));
        }
        #pragma unroll
        for (int off = 1; off <= 2; off <<= 1) {
            mx0 = fmaxf(mx0, __shfl_xor_sync(0xffffffffu, mx0, off));
            mx1 = fmaxf(mx1, __shfl_xor_sync(0xffffffffu, mx1, off));
        }
        float mnew0 = fmaxf(m0v, mx0);
        float mnew1 = fmaxf(m1v, mx1);
        float a0 = __expf(m0v - mnew0);
        float a1 = __expf(m1v - mnew1);
        m0v = mnew0; m1v = mnew1;

        uint32_t Ph[8][2], Pl[8][2];
        float rs0 = 0.f, rs1 = 0.f;
        #pragma unroll
        for (int nt = 0; nt < 8; nt++) {
            float p0 = __expf(S[nt][0] - mnew0);
            float p1 = __expf(S[nt][1] - mnew0);
            float p2 = __expf(S[nt][2] - mnew1);
            float p3 = __expf(S[nt][3] - mnew1);
            rs0 += p0 + p1;
            rs1 += p2 + p3;
            __nv_bfloat16 h0 = __float2bfloat16_rn(p0);
            __nv_bfloat16 h1 = __float2bfloat16_rn(p1);
            __nv_bfloat16 h2 = __float2bfloat16_rn(p2);
            __nv_bfloat16 h3 = __float2bfloat16_rn(p3);
            __nv_bfloat162 hA = __halves2bfloat162(h0, h1);
            __nv_bfloat162 hB = __halves2bfloat162(h2, h3);
            Ph[nt][0] = *(uint32_t*)&hA;
            Ph[nt][1] = *(uint32_t*)&hB;
            Pl[nt][0] = pack_bf16(p0 - __bfloat162float(h0), p1 - __bfloat162float(h1));
            Pl[nt][1] = pack_bf16(p2 - __bfloat162float(h2), p3 - __bfloat162float(h3));
        }
        #pragma unroll
        for (int off = 1; off <= 2; off <<= 1) {
            rs0 += __shfl_xor_sync(0xffffffffu, rs0, off);
            rs1 += __shfl_xor_sync(0xffffffffu, rs1, off);
        }
        l0v = l0v * a0 + rs0;
        l1v = l1v * a1 + rs1;
        #pragma unroll
        for (int nt = 0; nt < 8; nt++) {
            O[nt][0] *= a0; O[nt][1] *= a0;
            O[nt][2] *= a1; O[nt][3] *= a1;
        }

        #pragma unroll
        for (int ks = 0; ks < 4; ks++) {
            uint32_t aH[4] = {Ph[2*ks][0], Ph[2*ks][1], Ph[2*ks+1][0], Ph[2*ks+1][1]};
            uint32_t aL[4] = {Pl[2*ks][0], Pl[2*ks][1], Pl[2*ks+1][0], Pl[2*ks+1][1]};
            #pragma unroll
            for (int d16 = 0; d16 < 4; d16++) {
                uint32_t vh[4], vl[4];
                LDMX4T(vh, sb + FA_VH + lmKV + ks * (16 * FROWB) + d16 * 32);
                LDMX4T(vl, sb + FA_VL + lmKV + ks * (16 * FROWB) + d16 * 32);
                MMA16816(O[2*d16],   aH, vh[0], vh[1]);
                MMA16816(O[2*d16+1], aH, vh[2], vh[3]);
                MMA16816(O[2*d16],   aH, vl[0], vl[1]);
                MMA16816(O[2*d16+1], aH, vl[2], vl[3]);
                MMA16816(O[2*d16],   aL, vh[0], vh[1]);
                MMA16816(O[2*d16+1], aL, vh[2], vh[3]);
            }
        }
    }

    const float inv0 = 1.f / l0v;
    const float inv1 = 1.f / l1v;
    const int r0 = q0 + w * 16 + g;
    const int r1 = r0 + 8;
    #pragma unroll
    for (int nt = 0; nt < 8; nt++) {
        int dd = head * HD + nt * 8 + tig * 2;
        if (r0 < SEQ) {
            float2 o = make_float2(O[nt][0] * inv0, O[nt][1] * inv0);
            *(float2*)(out + ((size_t)batch * SEQ + r0) * HID + dd) = o;
        }
        if (r1 < SEQ) {
            float2 o = make_float2(O[nt][2] * inv1, O[nt][3] * inv1);
            *(float2*)(out + ((size_t)batch * SEQ + r1) * HID + dd) = o;
        }
    }
}

// ---------------------------------------------------------------------------
// Launch
// ---------------------------------------------------------------------------
extern "C" void kernel_launch(void* const* d_in, const int* in_sizes, int n_in,
                              void* d_out, int out_size)
{
    const float* X  = (const float*)d_in[0];
    const float* Wq = (const float*)d_in[1];
    const float* bq = (const float*)d_in[2];
    const float* Wk = (const float*)d_in[3];
    const float* bk = (const float*)d_in[4];
    const float* Wv = (const float*)d_in[5];
    const float* bv = (const float*)d_in[6];
    float* out = (float*)d_out;

    cudaFuncSetAttribute(qkv_mma,   cudaFuncAttributeMaxDynamicSharedMemorySize, QK_SMEM);
    cudaFuncSetAttribute(flash_mma, cudaFuncAttributeMaxDynamicSharedMemorySize, FA_SMEM);

    const size_t nconv = (size_t)NTOK * HID / 4 + (size_t)3 * HID * HID / 4;
    convert_planes<<<(unsigned)((nconv + 255) / 256), 256>>>(X, Wq, Wk, Wv);

    dim3 g1((NTOK + 127) / 128, 24);                 // 43 x 24
    qkv_mma<<<g1, 256, QK_SMEM>>>(bq, bk, bv);

    dim3 g2((SEQ + 127) / 128, BATCH * NH);          // 11 x 64
    flash_mma<<<g2, 256, FA_SMEM>>>(out);
}